// round 1
// baseline (speedup 1.0000x reference)
#include <cuda_runtime.h>
#include <stdint.h>

// SRP map: maps[f, g] = sum_p x[f, p, tau0[p, g]], then per-frame
// zero-mean + divide-by-max normalization.
//
// Key structural facts exploited:
//  * |tau lag| <= 5 (5cm array, 16kHz, c=343) -> wrapped lags live in
//    {0..5} U {507..511}. slot = tau & 15 maps the (guaranteed-margin)
//    set {0..7} U {504..511} bijectively to 0..15.
//  * So per frame only 144x16 x-values are needed (2 sectors per 2KB row):
//    DRAM x traffic 75.5MB -> 2.4MB.
//  * tau0 is frame-invariant: pre-packed once per launch into 4-bit slot
//    nibbles (147KB, L2-resident).
//  * smem gather layout xsm[slot*145 + p]: within a warp-LDS all lanes share
//    p, differ in slot; gcd(145,32)=1 -> distinct slots hit distinct banks,
//    equal slots broadcast -> conflict-free (1 cyc/warp-LDS).

#define NPAIR     144
#define KLEN      512
#define GPTS      2048          // RES_T * RES_P
#define THREADS   256
#define GPT       8             // grid points per thread
#define XS_STRIDE 145           // odd stride -> slot-injective mod 32 banks

// Packed tau slots: [pair][GPTS/8] words, 8 nibbles (grid points) per word.
__device__ uint32_t g_tau4[NPAIR * (GPTS / 8)];

__global__ void __launch_bounds__(256) pre_pack_kernel(const int* __restrict__ tau0) {
    int i = blockIdx.x * blockDim.x + threadIdx.x;   // word index
    if (i >= NPAIR * (GPTS / 8)) return;
    int p = i >> 8;          // / (GPTS/8)
    int w = i & 255;
    int base = p * GPTS + w * 8;
    uint32_t v = 0;
#pragma unroll
    for (int j = 0; j < 8; j++) {
        v |= (uint32_t)(tau0[base + j] & 15) << (4 * j);
    }
    g_tau4[i] = v;
}

__global__ void __launch_bounds__(THREADS) srp_main_kernel(
    const float* __restrict__ x, float* __restrict__ out)
{
    __shared__ float xsm[16 * XS_STRIDE];
    __shared__ float red_s[THREADS / 32];
    __shared__ float red_m[THREADS / 32];

    const int f   = blockIdx.x;
    const int tid = threadIdx.x;

    // ---- Load the 144x16 used x-values for this frame into smem ----
    const float* xf = x + (size_t)f * (NPAIR * KLEN);
    for (int i = tid; i < NPAIR * 16; i += THREADS) {
        int p = i >> 4;
        int j = i & 15;
        int k = (j < 8) ? j : (j + 496);   // slots 8..15 -> lags 504..511
        xsm[j * XS_STRIDE + p] = __ldg(&xf[p * KLEN + k]);
    }
    __syncthreads();

    // ---- Accumulate 8 grid points per thread over all 144 pairs ----
    float acc[GPT];
#pragma unroll
    for (int j = 0; j < GPT; j++) acc[j] = 0.0f;

    const uint32_t* tw = g_tau4 + tid;   // word for (pair p, this thread) at tw[p*256]
#pragma unroll 4
    for (int p = 0; p < NPAIR; p++) {
        uint32_t w = __ldg(&tw[p * (GPTS / 8)]);
#pragma unroll
        for (int j = 0; j < GPT; j++) {
            int slot = (w >> (4 * j)) & 15;
            acc[j] += xsm[slot * XS_STRIDE + p];
        }
    }

    // ---- Block reduction: sum and max over the 2048-point map ----
    float s = 0.0f;
    float m = -3.0e38f;
#pragma unroll
    for (int j = 0; j < GPT; j++) {
        s += acc[j];
        m = fmaxf(m, acc[j]);
    }
#pragma unroll
    for (int o = 16; o > 0; o >>= 1) {
        s += __shfl_xor_sync(0xFFFFFFFFu, s, o);
        m = fmaxf(m, __shfl_xor_sync(0xFFFFFFFFu, m, o));
    }
    int wid  = tid >> 5;
    int lane = tid & 31;
    if (lane == 0) { red_s[wid] = s; red_m[wid] = m; }
    __syncthreads();

    float tot = 0.0f;
    float mm  = -3.0e38f;
#pragma unroll
    for (int w = 0; w < THREADS / 32; w++) {
        tot += red_s[w];
        mm = fmaxf(mm, red_m[w]);
    }

    const float EPS  = 1e-12f;
    float mean = tot * (1.0f / (float)GPTS);
    float inv  = 1.0f / (mm - mean + EPS);

    // ---- Write normalized map ----
    float* of = out + (size_t)f * GPTS + tid * GPT;
#pragma unroll
    for (int j = 0; j < GPT; j++) {
        of[j] = (acc[j] - mean + EPS) * inv;
    }
}

extern "C" void kernel_launch(void* const* d_in, const int* in_sizes, int n_in,
                              void* d_out, int out_size)
{
    // Identify inputs by size for robustness (x is the big one).
    const float* x;
    const int*   tau0;
    if (in_sizes[0] == NPAIR * GPTS) {
        tau0 = (const int*)d_in[0];
        x    = (const float*)d_in[1];
    } else {
        x    = (const float*)d_in[0];
        tau0 = (const int*)d_in[1];
    }

    int nframes = out_size / GPTS;   // 256 for B=8, T=32

    int pack_words  = NPAIR * (GPTS / 8);
    int pack_blocks = (pack_words + 255) / 256;
    pre_pack_kernel<<<pack_blocks, 256>>>(tau0);

    srp_main_kernel<<<nframes, THREADS>>>(x, (float*)d_out);
}